// round 17
// baseline (speedup 1.0000x reference)
#include <cuda_runtime.h>
#include <cuda_fp16.h>
#include <cstdint>

// Problem constants
#define BB   8
#define CC   256
#define HH   128
#define WW   128
#define CRED 64
#define HW   (HH * WW)

// ---------------------------------------------------------------------------
// Scratch (__device__ globals).
// g_xt: x in NHWC fp16  [b][h][w][ci]
// g_wt: weights fp16    [tap][chunk(4)][cout(256)][ci(64)]
// g_T/R0/R127/C0/C127: per-(b,ci) image statistics for analytic pooling
// ---------------------------------------------------------------------------
__device__ float g_scale[BB * CC];
__device__ float g_T[BB * CC];
__device__ float g_R0[BB * CC];
__device__ float g_R127[BB * CC];
__device__ float g_C0[BB * CC];
__device__ float g_C127[BB * CC];
__device__ __align__(16) __half g_xt[(size_t)BB * HH * WW * CC];
__device__ __align__(16) __half g_wt[9 * 4 * 256 * 64];

// ---------------------------------------------------------------------------
// Helpers
// ---------------------------------------------------------------------------
__device__ __forceinline__ uint32_t smem_to_u32(const void* p) {
    uint32_t a;
    asm("{ .reg .u64 t; cvta.to.shared.u64 t, %1; cvt.u32.u64 %0, t; }"
        : "=r"(a) : "l"(p));
    return a;
}
#define SW128(off) ((off) ^ (((off) >> 3) & 0x70))

__device__ __forceinline__ void ldsm_x4(uint32_t& r0, uint32_t& r1,
                                        uint32_t& r2, uint32_t& r3, uint32_t addr) {
    asm volatile("ldmatrix.sync.aligned.m8n8.x4.shared.b16 {%0,%1,%2,%3}, [%4];"
                 : "=r"(r0), "=r"(r1), "=r"(r2), "=r"(r3) : "r"(addr));
}
__device__ __forceinline__ void mma16816(float* c, const uint32_t* a, const uint32_t* b) {
    asm volatile(
        "mma.sync.aligned.m16n8k16.row.col.f32.f16.f16.f32 "
        "{%0,%1,%2,%3}, {%4,%5,%6,%7}, {%8,%9}, {%0,%1,%2,%3};"
        : "+f"(c[0]), "+f"(c[1]), "+f"(c[2]), "+f"(c[3])
        : "r"(a[0]), "r"(a[1]), "r"(a[2]), "r"(a[3]), "r"(b[0]), "r"(b[1]));
}
__device__ __forceinline__ void cp_async16(uint32_t dst, const void* src) {
    asm volatile("cp.async.cg.shared.global [%0], [%1], 16;"
                 :: "r"(dst), "l"(src));
}
#define CP_COMMIT() asm volatile("cp.async.commit_group;")
#define CP_WAIT(n)  asm volatile("cp.async.wait_group %0;" :: "n"(n))

// ---------------------------------------------------------------------------
// Pre-pass 1: weights OIHW fp32 -> [tap][chunk4][cout][ci64] fp16; zero stats
// ---------------------------------------------------------------------------
__global__ __launch_bounds__(256)
void wt_conv_kernel(const float* __restrict__ w)
{
    const int idx = blockIdx.x * 256 + threadIdx.x;   // < 9*256*256
    if (idx < BB * CC) {
        g_T[idx] = 0.0f; g_R0[idx] = 0.0f; g_R127[idx] = 0.0f;
        g_C0[idx] = 0.0f; g_C127[idx] = 0.0f;
    }
    const int t  = idx >> 16;
    const int n  = (idx >> 8) & 255;
    const int ci = idx & 255;
    const float v = w[((long)n * CC + ci) * 9 + t];
    const int dst = (((t * 4 + (ci >> 6)) * 256) + n) * 64 + (ci & 63);
    g_wt[dst] = __float2half_rn(v);
}

// ---------------------------------------------------------------------------
// Pre-pass 2: x NCHW fp32 -> NHWC fp16 (smem transpose) + pooling stats
// ---------------------------------------------------------------------------
__global__ __launch_bounds__(256)
void xt_conv_kernel(const float* __restrict__ x)
{
    __shared__ float tile[64][130];
    const int ci0 = blockIdx.x * 64;
    const int h   = blockIdx.y;
    const int b   = blockIdx.z;
    const int tid = threadIdx.x;

#pragma unroll
    for (int i = 0; i < 32; i++) {
        int e = tid + i * 256;            // 0..8191
        int ci = e >> 7, w = e & 127;
        tile[ci][w] = x[(((long)b * CC + ci0 + ci) * HH + h) * WW + w];
    }
    __syncthreads();

    // ---- stats: per-ci row sum (4 lanes per ci), col-edge atomics ----
    {
        const int ci   = tid >> 2;        // 0..63
        const int part = tid & 3;
        float s = 0.0f;
        const float* tr = &tile[ci][part * 32];
#pragma unroll
        for (int w2 = 0; w2 < 32; w2++) s += tr[w2];
        s += __shfl_xor_sync(0xFFFFFFFFu, s, 1);
        s += __shfl_xor_sync(0xFFFFFFFFu, s, 2);
        const int gi = b * CC + ci0 + ci;
        if (part == 0) {
            atomicAdd(&g_T[gi], s);
            if (h == 0)   atomicAdd(&g_R0[gi], s);
            if (h == 127) atomicAdd(&g_R127[gi], s);
        } else if (part == 1) {
            atomicAdd(&g_C0[gi], tile[ci][0]);
        } else if (part == 2) {
            atomicAdd(&g_C127[gi], tile[ci][127]);
        }
    }

    const int w    = tid & 127;
    const int half = tid >> 7;            // ci subrange of 32
    const long ob  = (((long)b * HH + h) * WW + w) * CC + ci0 + half * 32;

    uint32_t pk[16];
#pragma unroll
    for (int j = 0; j < 16; j++) {
        __half2 hv = __floats2half2_rn(tile[half * 32 + 2 * j][w],
                                       tile[half * 32 + 2 * j + 1][w]);
        pk[j] = *(uint32_t*)&hv;
    }
    uint4* op = (uint4*)(g_xt + ob);
#pragma unroll
    for (int j = 0; j < 4; j++)
        op[j] = make_uint4(pk[4*j], pk[4*j+1], pk[4*j+2], pk[4*j+3]);
}

// ---------------------------------------------------------------------------
// SE (runs BEFORE conv): analytic pool from stats + fp32 weights, then FCs.
// pool[b,co] = bias[co] + (1/HW) * sum_{ci,t} w[co,ci,t] * S[b,ci,t]
// S from inclusion-exclusion on (T, R0, R127, C0, C127, corners).
// ---------------------------------------------------------------------------
__global__ __launch_bounds__(256)
void se_kernel(const float* __restrict__ x,  const float* __restrict__ w,
               const float* __restrict__ bd,
               const float* __restrict__ w1, const float* __restrict__ b1,
               const float* __restrict__ w2, const float* __restrict__ b2)
{
    __shared__ float S[CC][9];
    __shared__ float pool[CC];
    __shared__ float hbuf[CRED];
    const int b   = blockIdx.x;
    const int tid = threadIdx.x;

    // build S for ci = tid
    {
        const int gi = b * CC + tid;
        const float T  = g_T[gi];
        const float r0 = g_R0[gi],  r1 = g_R127[gi];
        const float c0 = g_C0[gi],  c1 = g_C127[gi];
        const long xb = ((long)gi) * HW;
        const float k00 = x[xb];                       // [0,0]
        const float k0W = x[xb + 127];                 // [0,127]
        const float kH0 = x[xb + 127 * WW];            // [127,0]
        const float kHW = x[xb + 127 * WW + 127];      // [127,127]
#pragma unroll
        for (int kh = 0; kh < 3; kh++) {
#pragma unroll
            for (int kw = 0; kw < 3; kw++) {
                const int dh = kh - 1, dw = kw - 1;
                float s = T;
                if (dh == 1)  s -= r0;
                if (dh == -1) s -= r1;
                if (dw == 1)  s -= c0;
                if (dw == -1) s -= c1;
                if (dh == 1 && dw == 1)   s += k00;
                if (dh == 1 && dw == -1)  s += k0W;
                if (dh == -1 && dw == 1)  s += kH0;
                if (dh == -1 && dw == -1) s += kHW;
                S[tid][kh * 3 + kw] = s;
            }
        }
    }
    __syncthreads();

    // pool for co = tid
    {
        float acc = 0.0f;
        const float* wr = w + (long)tid * CC * 9;
        for (int ci = 0; ci < CC; ci++) {
#pragma unroll
            for (int t = 0; t < 9; t++)
                acc = fmaf(wr[ci * 9 + t], S[ci][t], acc);
        }
        pool[tid] = acc * (1.0f / HW) + bd[tid];
    }
    __syncthreads();

    // FC1
    {
        const int j    = tid >> 2;
        const int part = tid & 3;
        float s = 0.0f;
        const float* wr = &w1[j * CC + part * 64];
        const float* pr = &pool[part * 64];
#pragma unroll 16
        for (int c2 = 0; c2 < 64; c2++) s = fmaf(pr[c2], wr[c2], s);
        s += __shfl_xor_sync(0xFFFFFFFFu, s, 1);
        s += __shfl_xor_sync(0xFFFFFFFFu, s, 2);
        if (part == 0) hbuf[j] = fmaxf(s + b1[j], 0.0f);
    }
    __syncthreads();

    // FC2 + sigmoid
    {
        float s = b2[tid];
        const float* wr = &w2[tid * CRED];
#pragma unroll 16
        for (int j = 0; j < CRED; j++) s = fmaf(hbuf[j], wr[j], s);
        g_scale[b * CC + tid] = 1.0f / (1.0f + __expf(-s));
    }
}

// ---------------------------------------------------------------------------
// Conv via mma.sync fp16 (fp32 acc). K=64 stages, double-buffered cp.async.
// Per CTA: (ntile, h, b) -> D[128 pixels, 128 couts].
// 36 stages: chunk(4 of 64ci) x kh(3) x kw(3); A restaged every 3 stages.
// Schedule: wait(0) -> sync -> compute kk=0 -> prefetch(s+1) -> kk=1..3.
// Epilogue applies (acc + bias) * se_scale and stores final output.
// ---------------------------------------------------------------------------
#define BBUF   16384            // B buffer stride (128*128)
#define ABASE  32768            // A buffers start
#define ABUF   16896            // A buffer stride (132*128)
#define SMEMSZ (ABASE + 2 * ABUF)   // 66560

__global__ __launch_bounds__(256, 2)
void conv_mma_kernel(const float* __restrict__ bias, float* __restrict__ y)
{
    extern __shared__ __align__(128) unsigned char smx[];
    const uint32_t s0 = smem_to_u32(smx);

    const int tid  = threadIdx.x;
    const int wid  = tid >> 5;
    const int lane = tid & 31;
    const int wm   = wid & 1;
    const int wn   = wid >> 1;
    const int n0   = blockIdx.x * 128;
    const int h    = blockIdx.y;
    const int b    = blockIdx.z;

    float acc[4][4][4];
#pragma unroll
    for (int mt = 0; mt < 4; mt++)
#pragma unroll
        for (int nt = 0; nt < 4; nt++)
#pragma unroll
            for (int r = 0; r < 4; r++) acc[mt][nt][r] = 0.0f;

    const int lrow = (lane & 7) + ((lane >> 3) & 1) * 8;
    const int lkcb = ((lane >> 4) * 8) * 2;   // 0 or 16 bytes

    auto do_stage_A = [&](int sa, int abuf) {
        const int c  = sa / 3;
        const int kh = sa % 3;
        const int hs = h + kh - 1;
        const bool hok = (hs >= 0) && (hs < HH);
        const uint32_t dA = s0 + ABASE + abuf * ABUF;
        const long base = ((long)(b * HH + (hok ? hs : 0)) * WW) * CC + (long)c * 64;
        for (int task = tid; task < 1040; task += 256) {
            const int r = task >> 3;
            const int q = task & 7;
            const int wsrc = r - 1;
            const uint32_t dst = dA + SW128((uint32_t)((r << 7) + q * 16));
            if (hok && wsrc >= 0 && wsrc < WW)
                cp_async16(dst, (const char*)(g_xt + base + (long)wsrc * CC) + q * 16);
            else
                *(uint4*)(smx + (dst - s0)) = make_uint4(0, 0, 0, 0);
        }
    };
    auto do_stage_B = [&](int s, int bbuf) {
        const int c = s / 9;
        const int t = s % 9;
        const uint32_t dB = s0 + bbuf * BBUF;
        const long base = ((long)(t * 4 + c) * 256 + n0) * 64;
#pragma unroll
        for (int r2 = 0; r2 < 4; r2++) {
            int i = tid + r2 * 256;
            int n = i >> 3, q = i & 7;
            cp_async16(dB + SW128((uint32_t)((n << 7) + q * 16)),
                       (const char*)g_wt + (base + (long)n * 64 + q * 8) * 2);
        }
    };

    do_stage_A(0, 0);
    do_stage_B(0, 0);
    CP_COMMIT();

    for (int s = 0; s < 36; s++) {
        const int sa = s / 3;
        const int kw = s % 3;

        CP_WAIT(0);
        __syncthreads();

        const uint32_t baseA = s0 + ABASE + (sa & 1) * ABUF;
        const uint32_t baseB = s0 + (s & 1) * BBUF;

#pragma unroll
        for (int kk = 0; kk < 4; kk++) {
            const uint32_t kb = (uint32_t)(kk * 32 + lkcb);
            uint32_t a[4][4], bf[4][2];
#pragma unroll
            for (int mt = 0; mt < 4; mt++) {
                const uint32_t rb = (uint32_t)((wm * 64 + mt * 16 + lrow + kw) << 7);
                ldsm_x4(a[mt][0], a[mt][1], a[mt][2], a[mt][3],
                        baseA + SW128(rb + kb));
            }
#pragma unroll
            for (int np = 0; np < 2; np++) {
                const uint32_t rb = (uint32_t)((wn * 32 + np * 16 + lrow) << 7);
                uint32_t r0, r1, r2, r3;
                ldsm_x4(r0, r1, r2, r3, baseB + SW128(rb + kb));
                bf[2*np][0] = r0;   bf[2*np][1] = r2;
                bf[2*np+1][0] = r1; bf[2*np+1][1] = r3;
            }
#pragma unroll
            for (int mt = 0; mt < 4; mt++)
#pragma unroll
                for (int nt = 0; nt < 4; nt++) mma16816(acc[mt][nt], a[mt], bf[nt]);

            // prefetch after the first k-step's work is issued
            if (kk == 0 && s < 35) {
                do_stage_B(s + 1, (s + 1) & 1);
                if (kw == 2)
                    do_stage_A(sa + 1, (sa + 1) & 1);
                CP_COMMIT();
            }
        }
    }

    // ---- epilogue: (acc + bias) * se_scale, store final ----
    const int r0 = lane >> 2;
    const int c0 = (lane & 3) * 2;
#pragma unroll
    for (int nt = 0; nt < 4; nt++) {
        const int co = n0 + wn * 32 + nt * 8 + c0;
        const float b0 = bias[co], b1 = bias[co + 1];
        const float s0s = g_scale[b * CC + co];
        const float s1s = g_scale[b * CC + co + 1];
#pragma unroll
        for (int mt = 0; mt < 4; mt++) {
            const int wpix = wm * 64 + mt * 16 + r0;
            long e0 = (((long)b * CC + co) * HH + h) * WW + wpix;
            y[e0]          = (acc[mt][nt][0] + b0) * s0s;
            y[e0 + HW]     = (acc[mt][nt][1] + b1) * s1s;
            y[e0 + 8]      = (acc[mt][nt][2] + b0) * s0s;
            y[e0 + HW + 8] = (acc[mt][nt][3] + b1) * s1s;
        }
    }
}

// ---------------------------------------------------------------------------
extern "C" void kernel_launch(void* const* d_in, const int* in_sizes, int n_in,
                              void* d_out, int out_size)
{
    const float* x  = (const float*)d_in[0];
    const float* wd = (const float*)d_in[1];
    const float* bd = (const float*)d_in[2];
    const float* w1 = (const float*)d_in[3];
    const float* b1 = (const float*)d_in[4];
    const float* w2 = (const float*)d_in[5];
    const float* b2 = (const float*)d_in[6];
    float* out = (float*)d_out;

    static int smem_set = 0;
    if (!smem_set) {
        cudaFuncSetAttribute(conv_mma_kernel,
                             cudaFuncAttributeMaxDynamicSharedMemorySize, SMEMSZ);
        smem_set = 1;
    }

    wt_conv_kernel<<<9 * CC * CC / 256, 256>>>(wd);
    xt_conv_kernel<<<dim3(CC / 64, HH, BB), 256>>>(x);
    se_kernel<<<BB, 256>>>(x, wd, bd, w1, b1, w2, b2);
    conv_mma_kernel<<<dim3(2, HH, BB), 256, SMEMSZ>>>(bd, out);
}